// round 12
// baseline (speedup 1.0000x reference)
#include <cuda_runtime.h>
#include <cstdio>
#include <math.h>

#define MAXN 32768

__device__ float g_loss[MAXN];

// Unfused cross product: matches XLA's mul-then-sub rounding (no FMA contraction).
__device__ __forceinline__ float crossf(float ex, float ey, float dx, float dy) {
    return __fsub_rn(__fmul_rn(ex, dy), __fmul_rn(ey, dx));
}

// Convex-hull edge relation (reference semantics):
//   succ[a] = first b != a with cross(b-a, c-a) >= -1e-7 for ALL c
template<int K>
__device__ __forceinline__ void hull_edges(const float* x, const float* y,
                                           int* succ, bool* on) {
    for (int a = 0; a < K; a++) {
        int sb = -1;
        float xa = x[a], ya = y[a];
        for (int b = 0; b < K; b++) {
            if (b == a) continue;
            float ex = __fsub_rn(x[b], xa), ey = __fsub_rn(y[b], ya);
            bool ok = true;
            for (int c = 0; c < K; c++) {
                float cr = crossf(ex, ey, __fsub_rn(x[c], xa), __fsub_rn(y[c], ya));
                if (cr < -1e-7f) { ok = false; break; }
            }
            if (ok) { sb = b; break; }
        }
        succ[a] = sb;
        on[a] = (sb >= 0);
    }
}

// Walk the CCW successor cycle into a 16-gon padded with the last visited vertex.
template<int K>
__device__ __forceinline__ void walk_hull(const float* x, const float* y,
                                          const int* succ, const bool* on,
                                          float* px, float* py) {
    int cnt = 0, start = -1;
    #pragma unroll
    for (int k = 0; k < K; k++)
        if (on[k]) { cnt++; if (start < 0) start = k; }
    int cur = (start < 0) ? 0 : start;
    for (int k = 0; k < 16; k++) {
        px[k] = x[cur]; py[k] = y[cur];
        if (k + 1 < cnt) {
            int nx = succ[cur];
            cur = (nx >= 0) ? nx : cur;  // guard: degenerate chains stall (pad-with-last)
        }
    }
}

__device__ __forceinline__ float shoelace16(const float* x, const float* y) {
    float s = 0.f;
    #pragma unroll
    for (int k = 0; k < 16; k++) {
        int j = (k + 1) & 15;
        s = __fadd_rn(s, __fsub_rn(__fmul_rn(x[k], y[j]), __fmul_rn(x[j], y[k])));
    }
    return 0.5f * s;
}

__global__ void __launch_bounds__(256) giou_kernel(const float* __restrict__ pred,
                                                   const float* __restrict__ target,
                                                   const float* __restrict__ weight,
                                                   int n) {
    int i = blockIdx.x * blockDim.x + threadIdx.x;
    if (i >= n) return;

    float Px[9], Py[9];
    #pragma unroll
    for (int k = 0; k < 9; k++) {
        Px[k] = pred[i * 18 + 2 * k];
        Py[k] = pred[i * 18 + 2 * k + 1];
    }
    float Tx[4], Ty[4];
    #pragma unroll
    for (int k = 0; k < 4; k++) {
        Tx[k] = target[i * 8 + 2 * k];
        Ty[k] = target[i * 8 + 2 * k + 1];
    }

    // target signed area + CCW orientation
    float sa = 0.f;
    #pragma unroll
    for (int k = 0; k < 4; k++) {
        int j = (k + 1) & 3;
        sa = __fadd_rn(sa, __fsub_rn(__fmul_rn(Tx[k], Ty[j]), __fmul_rn(Tx[j], Ty[k])));
    }
    sa *= 0.5f;
    float Cx[4], Cy[4];
    #pragma unroll
    for (int k = 0; k < 4; k++) {
        int s = (sa < 0.f) ? (3 - k) : k;
        Cx[k] = Tx[s]; Cy[k] = Ty[s];
    }
    float areaB = fabsf(sa);

    // hull of pred (9 pts) -> walked padded 16-gon (matches reference's padded hull)
    int succ9[9]; bool on9[9];
    hull_edges<9>(Px, Py, succ9, on9);
    float sx[16], sy[16];
    walk_hull<9>(Px, Py, succ9, on9, sx, sy);
    float areaA = fabsf(shoelace16(sx, sy));

    // Sutherland-Hodgman vs 4 CCW target edges, fixed S=16 (reference semantics)
    for (int e = 0; e < 4; e++) {
        float ax = Cx[e], ay = Cy[e];
        int en = (e + 1) & 3;
        float ex = __fsub_rn(Cx[en], ax), ey = __fsub_rn(Cy[en], ay);

        float ox[16], oy[16];
        int m = 0;
        float fx = 0.f, fy = 0.f;

        for (int k = 0; k < 16; k++) {
            int kn = (k + 1) & 15;
            float px = sx[k],  py = sy[k];
            float qx = sx[kn], qy = sy[kn];
            float dp = crossf(ex, ey, __fsub_rn(px, ax), __fsub_rn(py, ay));
            float dq = crossf(ex, ey, __fsub_rn(qx, ax), __fsub_rn(qy, ay));
            bool ip = (dp >= 0.f), iq = (dq >= 0.f);
            float den = __fsub_rn(dp, dq);
            float t = dp / ((fabsf(den) < 1e-9f) ? 1e-9f : den);
            float ix = __fadd_rn(px, __fmul_rn(t, __fsub_rn(qx, px)));
            float iy = __fadd_rn(py, __fmul_rn(t, __fsub_rn(qy, py)));
            if (k == 0) { fx = ix; fy = iy; }   // fallback when nothing emitted
            if (ip != iq) { if (m < 16) { ox[m] = ix; oy[m] = iy; } m++; }
            if (iq)       { if (m < 16) { ox[m] = qx; oy[m] = qy; } m++; }
        }

        if (m == 0) {
            for (int j = 0; j < 16; j++) { ox[j] = fx; oy[j] = fy; }
        } else if (m < 16) {
            float lx = ox[m - 1], ly = oy[m - 1];
            for (int j = m; j < 16; j++) { ox[j] = lx; oy[j] = ly; }
        }
        for (int j = 0; j < 16; j++) { sx[j] = ox[j]; sy[j] = oy[j]; }
    }

    float inter = fabsf(shoelace16(sx, sy));
    // Mathematically inter <= min(areaA, areaB) for correct clipping; clamp is a
    // no-op on correct geometry but prevents /1e-9 explosion on degenerate cases.
    inter = fminf(inter, fminf(areaA, areaB));

    // hull of pred+target (13 pts)
    float Ux[13], Uy[13];
    #pragma unroll
    for (int k = 0; k < 9; k++) { Ux[k] = Px[k]; Uy[k] = Py[k]; }
    #pragma unroll
    for (int k = 0; k < 4; k++) { Ux[9 + k] = Tx[k]; Uy[9 + k] = Ty[k]; }
    int succ13[13]; bool on13[13];
    hull_edges<13>(Ux, Uy, succ13, on13);
    float hx[16], hy[16];
    walk_hull<13>(Ux, Uy, succ13, on13, hx, hy);
    float areaC = fabsf(shoelace16(hx, hy));

    float uni  = areaA + areaB - inter;
    float giou = inter / fmaxf(uni, 1e-9f) - (areaC - uni) / fmaxf(areaC, 1e-9f);
    // Reference giou is always in (-1, 1]; clamp bounds damage from degenerate cases.
    giou = fminf(fmaxf(giou, -1.f), 1.f);

    g_loss[i] = (1.f - giou) * weight[i];
}

__global__ void reduce_kernel(float* __restrict__ out, int n, int out_size) {
    __shared__ double sh[256];
    double s = 0.0;
    for (int i = threadIdx.x; i < n; i += 256) s += (double)g_loss[i];
    sh[threadIdx.x] = s;
    __syncthreads();
    for (int st = 128; st > 0; st >>= 1) {
        if (threadIdx.x < st) sh[threadIdx.x] += sh[threadIdx.x + st];
        __syncthreads();
    }
    if (threadIdx.x == 0) {
        float mean = (float)(sh[0] / (double)n);
        for (int j = 0; j < out_size; j++) out[j] = mean;
    }
}

extern "C" void kernel_launch(void* const* d_in, const int* in_sizes, int n_in,
                              void* d_out, int out_size) {
    // Map inputs by element count: pred=18n (largest), target=8n, weight=n (smallest).
    int mx = 0, mn = 0;
    for (int k = 1; k < n_in; k++) {
        if (in_sizes[k] > in_sizes[mx]) mx = k;
        if (in_sizes[k] < in_sizes[mn]) mn = k;
    }
    int ip = mx, iw = mn, it = 0;
    for (int k = 0; k < n_in; k++)
        if (k != ip && k != iw) { it = k; break; }

    const float* pred   = (const float*)d_in[ip];
    const float* target = (const float*)d_in[it];
    const float* weight = (const float*)d_in[iw];
    float* out = (float*)d_out;

    int n = in_sizes[iw];
    if (n > MAXN) n = MAXN;

    giou_kernel<<<(n + 255) / 256, 256>>>(pred, target, weight, n);
    reduce_kernel<<<1, 256>>>(out, n, out_size);

    // Diagnostic tap: identical kernel launches on every call; host-side
    // readback only on non-capturing calls; echoed only if rc != 0.
    cudaStreamCaptureStatus cs = cudaStreamCaptureStatusNone;
    cudaStreamIsCapturing((cudaStream_t)0, &cs);
    if (cs == cudaStreamCaptureStatusNone) {
        static float hl[MAXN];
        cudaDeviceSynchronize();
        cudaMemcpyFromSymbol(hl, g_loss, (size_t)n * 4);
        double s = 0.0; int bad = 0;
        double lmin = 1e300, lmax = -1e300;
        for (int k = 0; k < n; k++) {
            if (isfinite(hl[k])) {
                s += hl[k];
                if (hl[k] < lmin) lmin = hl[k];
                if (hl[k] > lmax) lmax = hl[k];
            } else bad++;
        }
        fprintf(stderr, "DIAG r12: mean=%.8e nonfinite=%d min=%.4e max=%.4e first4: %.4f %.4f %.4f %.4f\n",
                s / n, bad, lmin, lmax, hl[0], hl[1], hl[2], hl[3]);
        fflush(stderr);
    }
}

// round 13
// speedup vs baseline: 3.6105x; 3.6105x over previous
#include <cuda_runtime.h>
#include <math.h>

#define MAXN 32768
#define NTHREADS 256

__device__ float g_part[256];

// Jarvis gift-wrap of K points -> CCW hull vertex cycle.
// Fills hx/hy[0..h-1], returns h, and accumulates 2*signed area into *s2out.
template<int K>
__device__ __forceinline__ int wrap_hull(const float* x, const float* y,
                                         float* hx, float* hy, float* s2out) {
    int start = 0;
    #pragma unroll
    for (int k = 1; k < K; k++)
        if (y[k] < y[start] || (y[k] == y[start] && x[k] < x[start])) start = k;

    float s2 = 0.f;
    int h = 0, cur = start;
    for (int it = 0; it < K; it++) {
        hx[h] = x[cur]; hy[h] = y[cur]; h++;
        float cx = x[cur], cy = y[cur];
        int nxt = (cur == 0) ? 1 : 0;
        float ex = x[nxt] - cx, ey = y[nxt] - cy;
        #pragma unroll
        for (int c = 0; c < K; c++) {
            if (c == cur) continue;
            float cr = ex * (y[c] - cy) - ey * (x[c] - cx);
            if (cr < 0.f) { nxt = c; ex = x[c] - cx; ey = y[c] - cy; }
        }
        s2 += cx * y[nxt] - x[nxt] * cy;
        cur = nxt;
        if (cur == start) break;
    }
    *s2out = s2;
    return h;
}

// Area-only gift wrap (no vertex storage) for the pred+target hull.
template<int K>
__device__ __forceinline__ float wrap_area(const float* x, const float* y) {
    int start = 0;
    #pragma unroll
    for (int k = 1; k < K; k++)
        if (y[k] < y[start] || (y[k] == y[start] && x[k] < x[start])) start = k;

    float s2 = 0.f;
    int cur = start;
    for (int it = 0; it < K; it++) {
        float cx = x[cur], cy = y[cur];
        int nxt = (cur == 0) ? 1 : 0;
        float ex = x[nxt] - cx, ey = y[nxt] - cy;
        #pragma unroll
        for (int c = 0; c < K; c++) {
            if (c == cur) continue;
            float cr = ex * (y[c] - cy) - ey * (x[c] - cx);
            if (cr < 0.f) { nxt = c; ex = x[c] - cx; ey = y[c] - cy; }
        }
        s2 += cx * y[nxt] - x[nxt] * cy;
        cur = nxt;
        if (cur == start) break;
    }
    return 0.5f * fabsf(s2);
}

__global__ void __launch_bounds__(NTHREADS) giou_kernel(const float* __restrict__ pred,
                                                        const float* __restrict__ target,
                                                        const float* __restrict__ weight,
                                                        int n) {
    int i = blockIdx.x * blockDim.x + threadIdx.x;
    float loss = 0.f;

    if (i < n) {
        float Px[9], Py[9];
        const float2* p2 = (const float2*)(pred) + (size_t)i * 9;
        #pragma unroll
        for (int k = 0; k < 9; k++) {
            float2 v = p2[k];
            Px[k] = v.x; Py[k] = v.y;
        }
        float Tx[4], Ty[4];
        const float2* t2 = (const float2*)(target) + (size_t)i * 4;
        #pragma unroll
        for (int k = 0; k < 4; k++) {
            float2 v = t2[k];
            Tx[k] = v.x; Ty[k] = v.y;
        }

        // target signed area + CCW orientation
        float sa = 0.f;
        #pragma unroll
        for (int k = 0; k < 4; k++) {
            int j = (k + 1) & 3;
            sa += Tx[k] * Ty[j] - Tx[j] * Ty[k];
        }
        sa *= 0.5f;
        float Cx[4], Cy[4];
        #pragma unroll
        for (int k = 0; k < 4; k++) {
            int s = (sa < 0.f) ? (3 - k) : k;
            Cx[k] = Tx[s]; Cy[k] = Ty[s];
        }
        float areaB = fabsf(sa);

        // hull of pred (CCW cycle + area in one pass)
        float sx[16], sy[16], s2A;
        int m = wrap_hull<9>(Px, Py, sx, sy, &s2A);
        float areaA = 0.5f * fabsf(s2A);

        // Sutherland-Hodgman vs 4 CCW target edges, dynamic vertex count.
        // (Clipping the true h-gon == clipping the reference's padded 16-gon:
        //  pad duplicates are emission-neutral.)
        for (int e = 0; e < 4 && m > 0; e++) {
            float ax = Cx[e], ay = Cy[e];
            int en = (e + 1) & 3;
            float ex = Cx[en] - ax, ey = Cy[en] - ay;

            float d[16];
            for (int k = 0; k < m; k++)
                d[k] = ex * (sy[k] - ay) - ey * (sx[k] - ax);

            float ox[16], oy[16];
            int mo = 0;
            for (int k = 0; k < m; k++) {
                int kn = (k + 1 == m) ? 0 : k + 1;
                float dp = d[k], dq = d[kn];
                bool ip = (dp >= 0.f), iq = (dq >= 0.f);
                if (ip != iq) {
                    float den = dp - dq;
                    float t = dp / ((fabsf(den) < 1e-9f) ? 1e-9f : den);
                    if (mo < 16) {
                        ox[mo] = sx[k] + t * (sx[kn] - sx[k]);
                        oy[mo] = sy[k] + t * (sy[kn] - sy[k]);
                        mo++;
                    }
                }
                if (iq && mo < 16) { ox[mo] = sx[kn]; oy[mo] = sy[kn]; mo++; }
            }
            for (int j = 0; j < mo; j++) { sx[j] = ox[j]; sy[j] = oy[j]; }
            m = mo;
        }

        float inter = 0.f;
        for (int k = 0; k < m; k++) {
            int j = (k + 1 == m) ? 0 : k + 1;
            inter += sx[k] * sy[j] - sx[j] * sy[k];
        }
        inter = 0.5f * fabsf(inter);
        // true for correct clipping; firewall for degenerate cases
        inter = fminf(inter, fminf(areaA, areaB));

        // hull of pred+target (area only)
        float Ux[13], Uy[13];
        #pragma unroll
        for (int k = 0; k < 9; k++) { Ux[k] = Px[k]; Uy[k] = Py[k]; }
        #pragma unroll
        for (int k = 0; k < 4; k++) { Ux[9 + k] = Tx[k]; Uy[9 + k] = Ty[k]; }
        float areaC = wrap_area<13>(Ux, Uy);

        float uni  = areaA + areaB - inter;
        float giou = inter / fmaxf(uni, 1e-9f) - (areaC - uni) / fmaxf(areaC, 1e-9f);
        giou = fminf(fmaxf(giou, -1.f), 1.f);  // reference giou is in (-1, 1]

        loss = (1.f - giou) * weight[i];
    }

    // deterministic per-block tree reduction
    __shared__ float sh[NTHREADS];
    sh[threadIdx.x] = loss;
    __syncthreads();
    #pragma unroll
    for (int st = NTHREADS / 2; st > 0; st >>= 1) {
        if (threadIdx.x < st) sh[threadIdx.x] += sh[threadIdx.x + st];
        __syncthreads();
    }
    if (threadIdx.x == 0) g_part[blockIdx.x] = sh[0];
}

__global__ void final_reduce(float* __restrict__ out, int nblocks, int n, int out_size) {
    __shared__ double sh[256];
    int t = threadIdx.x;
    sh[t] = (t < nblocks) ? (double)g_part[t] : 0.0;
    __syncthreads();
    #pragma unroll
    for (int st = 128; st > 0; st >>= 1) {
        if (t < st) sh[t] += sh[t + st];
        __syncthreads();
    }
    if (t == 0) {
        float mean = (float)(sh[0] / (double)n);
        for (int j = 0; j < out_size; j++) out[j] = mean;
    }
}

extern "C" void kernel_launch(void* const* d_in, const int* in_sizes, int n_in,
                              void* d_out, int out_size) {
    // Map inputs by element count: pred=18n (largest), target=8n, weight=n (smallest).
    int mx = 0, mn = 0;
    for (int k = 1; k < n_in; k++) {
        if (in_sizes[k] > in_sizes[mx]) mx = k;
        if (in_sizes[k] < in_sizes[mn]) mn = k;
    }
    int ip = mx, iw = mn, it = 0;
    for (int k = 0; k < n_in; k++)
        if (k != ip && k != iw) { it = k; break; }

    const float* pred   = (const float*)d_in[ip];
    const float* target = (const float*)d_in[it];
    const float* weight = (const float*)d_in[iw];
    float* out = (float*)d_out;

    int n = in_sizes[iw];
    if (n > MAXN) n = MAXN;

    int blocks = (n + NTHREADS - 1) / NTHREADS;   // 128 for n=32768
    giou_kernel<<<blocks, NTHREADS>>>(pred, target, weight, n);
    final_reduce<<<1, 256>>>(out, blocks, n, out_size);
}